// round 2
// baseline (speedup 1.0000x reference)
#include <cuda_runtime.h>

// EfficientInteractionBilinear — fused SIMT fp32 baseline.
// out[n,u] = sum_{i,e} A[n,i,e] * W[e,i,u]
//   A[n,i,e] = sum_s rbf[n,i,s] * S[n,s,e]
//   S[n,s,e] = sum_k sph[n,s,k] * m2[n,k,e],  m2 scattered from m via (id_reduce, Kidx)

#define NSPH     16
#define KMAXC    16
#define EMB      64
#define INTERM   64
#define UOUT     128
#define M_TILE   32
#define NTHREADS 256
#define MAX_EDGES 65536

// device scratch (no allocations allowed)
__device__ int g_tri[MAX_EDGES * KMAXC];
__device__ int g_idx64;

// Detect whether index arrays are int64 or int32. For int64 (little-endian,
// small non-negative values) every odd 32-bit word of Kidx is zero; for int32
// Kidx contains nonzero odd words (slot indices 1,3,5,...).
__global__ void detect_idx_dtype(const int* __restrict__ kidx_words, int nt)
{
    if (blockIdx.x == 0 && threadIdx.x == 0) {
        int n = nt < 128 ? nt : 128;
        int flag = 1;
        for (int t = 0; t < n; ++t)
            if (kidx_words[2 * t + 1] != 0) { flag = 0; break; }
        g_idx64 = flag;
    }
}

__global__ void init_map(int ne)
{
    int idx = blockIdx.x * blockDim.x + threadIdx.x;
    if (idx < ne * KMAXC) g_tri[idx] = -1;
}

__global__ void scatter_map(const void* __restrict__ idr_raw,
                            const void* __restrict__ kidx_raw, int nt, int ne)
{
    int t = blockIdx.x * blockDim.x + threadIdx.x;
    if (t >= nt) return;
    long long e, k;
    if (g_idx64) {
        e = ((const long long*)idr_raw)[t];
        k = ((const long long*)kidx_raw)[t];
    } else {
        e = (long long)((const int*)idr_raw)[t];
        k = (long long)((const int*)kidx_raw)[t];
    }
    if (e >= 0 && e < ne && k >= 0 && k < KMAXC)
        g_tri[(int)e * KMAXC + (int)k] = t;
}

struct SmemLayout {
    float S[M_TILE][NSPH][EMB];   // 128 KB  per-edge S matrices
    float W[EMB][UOUT];           //  32 KB  W slice for current i
    float A[M_TILE][EMB];         //   8 KB  A chunk for current i
    float R[M_TILE][NSPH];        //   2 KB  rbf slice for current i
    float m2[KMAXC][EMB];         //   4 KB  staged neighbor rows (one edge)
    float sphE[NSPH][KMAXC];      //   1 KB  sph for one edge
    int   tri[M_TILE][KMAXC];     //   2 KB  triplet map for tile
};

__device__ __forceinline__ void cp_async16(void* smem_dst, const void* gmem_src)
{
    unsigned saddr = (unsigned)__cvta_generic_to_shared(smem_dst);
    asm volatile("cp.async.cg.shared.global [%0], [%1], 16;\n"
                 :: "r"(saddr), "l"(gmem_src));
}

__global__ __launch_bounds__(NTHREADS, 1)
void eib_main(const float* __restrict__ rbf, const float* __restrict__ sph,
              const float* __restrict__ m, const float* __restrict__ wgt,
              float* __restrict__ out, int ne)
{
    extern __shared__ char smem_raw[];
    SmemLayout& sm = *reinterpret_cast<SmemLayout*>(smem_raw);
    const int tid = threadIdx.x;
    const int edge0 = blockIdx.x * M_TILE;

    // stage triplet map for this tile
    for (int j = tid; j < M_TILE * KMAXC; j += NTHREADS) {
        int me = j >> 4;
        int n = edge0 + me;
        sm.tri[me][j & 15] = (n < ne) ? g_tri[n * KMAXC + (j & 15)] : -1;
    }
    __syncthreads();

    // ---------------- Phase A: S[me][s][e] = sum_k sph[s][k] * m2[k][e] ----
    const int pk = tid >> 4;          // 0..15 (serves as k for load, s for compute)
    const int pe = (tid & 15) * 4;    // e offset (float4)
    for (int me = 0; me < M_TILE; ++me) {
        int n = edge0 + me;
        {
            float4 v = make_float4(0.f, 0.f, 0.f, 0.f);
            int t = sm.tri[me][pk];
            if (t >= 0)
                v = *reinterpret_cast<const float4*>(&m[(size_t)t * EMB + pe]);
            *reinterpret_cast<float4*>(&sm.m2[pk][pe]) = v;
            sm.sphE[pk][tid & 15] = (n < ne)
                ? sph[(size_t)n * (NSPH * KMAXC) + pk * KMAXC + (tid & 15)] : 0.f;
        }
        __syncthreads();
        {
            float4 acc = make_float4(0.f, 0.f, 0.f, 0.f);
            #pragma unroll
            for (int k = 0; k < KMAXC; ++k) {
                float c = sm.sphE[pk][k];
                float4 mv = *reinterpret_cast<const float4*>(&sm.m2[k][pe]);
                acc.x += c * mv.x; acc.y += c * mv.y;
                acc.z += c * mv.z; acc.w += c * mv.w;
            }
            *reinterpret_cast<float4*>(&sm.S[me][pk][pe]) = acc;
        }
        __syncthreads();
    }

    // ---------------- Main loop over i: build A chunk, GEMM vs W_i ---------
    // GEMM thread tile: 4 edges x 4 units. Warp spans 16 edges x 32 units so
    // per-e unique smem traffic per warp is 64B (A) + 128B (W) -> crossbar-light.
    const int wid = tid >> 5, lane = tid & 31;
    const int wu = wid & 3, wm = wid >> 2;     // 4 warps along u, 2 along edges
    const int lu = lane & 7, lm = lane >> 3;
    const int me0 = (wm * 4 + lm) * 4;         // 0..28
    const int u0 = (wu * 8 + lu) * 4;          // 0..124
    const int ca_me = tid >> 3;                // computeA: edge 0..31
    const int ca_e = (tid & 7) * 8;            // computeA: e block

    float acc[4][4];
    #pragma unroll
    for (int j = 0; j < 4; ++j)
        #pragma unroll
        for (int t = 0; t < 4; ++t) acc[j][t] = 0.f;

    for (int i = 0; i < INTERM; ++i) {
        // async-stage W[:, i, :] (latency hidden behind computeA)
        #pragma unroll
        for (int r = 0; r < 8; ++r) {
            int jj = tid + r * NTHREADS;        // float4 index 0..2047
            int e = jj >> 5, u = (jj & 31) * 4;
            cp_async16(&sm.W[e][u], &wgt[((size_t)e * INTERM + i) * UOUT + u]);
        }
        asm volatile("cp.async.commit_group;\n" ::: "memory");

        // stage rbf[:, i, :]
        #pragma unroll
        for (int r = 0; r < 2; ++r) {
            int jj = tid + r * NTHREADS;
            int me = jj >> 4, s = jj & 15;
            int n = edge0 + me;
            sm.R[me][s] = (n < ne)
                ? rbf[(size_t)n * (INTERM * NSPH) + (size_t)i * NSPH + s] : 0.f;
        }
        __syncthreads();   // R ready (W still in flight)

        // A[me][e] = sum_s R[me][s] * S[me][s][e]
        {
            float4 r0 = make_float4(0,0,0,0), r1 = make_float4(0,0,0,0);
            #pragma unroll
            for (int s = 0; s < NSPH; ++s) {
                float c = sm.R[ca_me][s];
                float4 s0 = *reinterpret_cast<const float4*>(&sm.S[ca_me][s][ca_e]);
                float4 s1 = *reinterpret_cast<const float4*>(&sm.S[ca_me][s][ca_e + 4]);
                r0.x += c * s0.x; r0.y += c * s0.y; r0.z += c * s0.z; r0.w += c * s0.w;
                r1.x += c * s1.x; r1.y += c * s1.y; r1.z += c * s1.z; r1.w += c * s1.w;
            }
            *reinterpret_cast<float4*>(&sm.A[ca_me][ca_e]) = r0;
            *reinterpret_cast<float4*>(&sm.A[ca_me][ca_e + 4]) = r1;
        }
        asm volatile("cp.async.wait_group 0;\n" ::: "memory");
        __syncthreads();   // A and W ready

        // acc[4me][4u] += A[me0..+3][e] * W[e][u0..+3]
        #pragma unroll
        for (int eb = 0; eb < EMB; eb += 4) {
            float aM[4][4];
            #pragma unroll
            for (int j = 0; j < 4; ++j) {
                float4 av = *reinterpret_cast<const float4*>(&sm.A[me0 + j][eb]);
                aM[j][0] = av.x; aM[j][1] = av.y; aM[j][2] = av.z; aM[j][3] = av.w;
            }
            #pragma unroll
            for (int t = 0; t < 4; ++t) {
                float4 w = *reinterpret_cast<const float4*>(&sm.W[eb + t][u0]);
                #pragma unroll
                for (int j = 0; j < 4; ++j) {
                    acc[j][0] += aM[j][t] * w.x;
                    acc[j][1] += aM[j][t] * w.y;
                    acc[j][2] += aM[j][t] * w.z;
                    acc[j][3] += aM[j][t] * w.w;
                }
            }
        }
        __syncthreads();   // before W/A overwritten next i
    }

    #pragma unroll
    for (int j = 0; j < 4; ++j) {
        int n = edge0 + me0 + j;
        if (n < ne) {
            float4 o = make_float4(acc[j][0], acc[j][1], acc[j][2], acc[j][3]);
            *reinterpret_cast<float4*>(&out[(size_t)n * UOUT + u0]) = o;
        }
    }
}

extern "C" void kernel_launch(void* const* d_in, const int* in_sizes, int n_in,
                              void* d_out, int out_size)
{
    const float* rbf = (const float*)d_in[0];
    const float* sph = (const float*)d_in[1];
    const float* m   = (const float*)d_in[2];
    const float* wgt = (const float*)d_in[3];
    const void*  idr = d_in[4];
    const void*  kid = d_in[5];

    int ne = in_sizes[0] / (INTERM * NSPH);
    int nt = in_sizes[4];

    detect_idx_dtype<<<1, 32>>>((const int*)kid, nt);
    init_map<<<(ne * KMAXC + 255) / 256, 256>>>(ne);
    scatter_map<<<(nt + 255) / 256, 256>>>(idr, kid, nt, ne);

    // idempotent; first (non-captured) correctness call makes it stick
    cudaFuncSetAttribute(eib_main, cudaFuncAttributeMaxDynamicSharedMemorySize,
                         (int)sizeof(SmemLayout));

    int grid = (ne + M_TILE - 1) / M_TILE;
    eib_main<<<grid, NTHREADS, sizeof(SmemLayout)>>>(rbf, sph, m, wgt,
                                                     (float*)d_out, ne);
}